// round 13
// baseline (speedup 1.0000x reference)
#include <cuda_runtime.h>
#include <cuda_fp16.h>
#include <stdint.h>

#define BLK 128
#define GRID 888

// ---------------- fragment image offsets (uint32 units) ----------------
// Per layer: [NT][KT][lane(32)][2 regs], single f16 term
constexpr int C_H  = 0;      // composite HT*L0: NT4 KT3 -> 768
constexpr int L1_H = 768;    // NT6 KT2 -> 768
constexpr int L2_H = 1536;   // NT5 KT3 -> 960
constexpr int L3_H = 2496;   // NT4 KT3 -> 768
constexpr int GW_H = 3264;   // NT16 KT2 -> 2048
// biases (float units, same 4B array)
constexpr int B_C = 5312, B_L1 = 5344, B_L2 = 5392, B_L3 = 5432, B_GW = 5464;
constexpr int HEADW = 5592;  // pw[30], pb at 5622
constexpr int SWTOT = 5624;  // 22,496 bytes

__device__ uint32_t g_wf[SWTOT];

__device__ __forceinline__ uint32_t pack_f16(float lo, float hi) {
    uint32_t r; asm("cvt.rn.f16x2.f32 %0, %1, %2;" : "=r"(r) : "f"(hi), "f"(lo)); return r;
}

// ---------------- prep kernel: fold -> f16 B-fragment layout ----------------
__global__ void prep_kernel(
    const float* __restrict__ ht_W, const float* __restrict__ ht_b,
    const float* __restrict__ m_W0, const float* __restrict__ m_b0,
    const float* __restrict__ m_W1, const float* __restrict__ m_b1,
    const float* __restrict__ m_W2, const float* __restrict__ m_b2,
    const float* __restrict__ m_W3, const float* __restrict__ m_b3,
    const float* __restrict__ gW,   const float* __restrict__ gb,
    const float* __restrict__ p1W,  const float* __restrict__ p1b,
    const float* __restrict__ p2W,  const float* __restrict__ p2b)
{
    const int tid = threadIdx.x;
    const int NTH = blockDim.x;

    auto fill = [&](int baseH, int NT, int KT, auto getw) {
        for (int i = tid; i < NT * KT * 64; i += NTH) {
            int reg = i & 1, ln = (i >> 1) & 31, tk = i >> 6;
            int kt = tk % KT, nt = tk / KT;
            int nn = nt * 8 + (ln >> 2);
            int k0 = kt * 16 + (ln & 3) * 2 + reg * 8;
            g_wf[baseH + i] = pack_f16(getw(nn, k0), getw(nn, k0 + 1));
        }
    };

    // composite Wc = W0eff @ ht_W  (30 x 38), exact fp32 fold
    fill(C_H, 4, 3, [&](int n, int k) {
        if (n >= 30 || k >= 38) return 0.0f;
        float s = 0.0f;
        for (int m = 0; m < 30; ++m)
            s += (m_W0[n * 60 + m] + m_W0[n * 60 + 30 + m]) * ht_W[m * 38 + k];
        return s; });
    fill(L1_H, 6, 2, [&](int n, int k) {
        return (n < 45 && k < 30) ? m_W1[n * 30 + k] : 0.0f; });
    fill(L2_H, 5, 3, [&](int n, int k) {
        return (n < 40 && k < 45) ? m_W2[n * 45 + k] : 0.0f; });
    fill(L3_H, 4, 3, [&](int n, int k) {
        return (n < 30 && k < 40) ? m_W3[n * 40 + k] : 0.0f; });
    fill(GW_H, 16, 2, [&](int n, int k) {
        int g = n >> 5, jj = n & 31;
        return (jj < 30 && k < 30) ? gW[(g * 30 + jj) * 30 + k] : 0.0f; });

    float* gf = reinterpret_cast<float*>(g_wf);
    for (int i = tid; i < 32; i += NTH) {
        float s = 0.0f;
        if (i < 30) {
            s = m_b0[i];
            for (int m = 0; m < 30; ++m)
                s += (m_W0[i * 60 + m] + m_W0[i * 60 + 30 + m]) * ht_b[m];
        }
        gf[B_C + i] = s;
    }
    for (int i = tid; i < 48; i += NTH)  gf[B_L1 + i] = (i < 45) ? m_b1[i] : 0.0f;
    for (int i = tid; i < 40; i += NTH)  gf[B_L2 + i] = m_b2[i];
    for (int i = tid; i < 32; i += NTH)  gf[B_L3 + i] = (i < 30) ? m_b3[i] : 0.0f;
    for (int i = tid; i < 128; i += NTH) {
        int g = i >> 5, jj = i & 31;
        gf[B_GW + i] = (jj < 30) ? gb[g * 30 + jj] : 0.0f;
    }
    for (int k = tid; k < 30; k += NTH) {
        float s = 0.0f;
        for (int i = 0; i < 10; ++i) s += p2W[i] * p1W[i * 30 + k];
        gf[HEADW + k] = s;
    }
    if (tid == 0) {
        float s = p2b[0];
        for (int i = 0; i < 10; ++i) s += p2W[i] * p1b[i];
        gf[HEADW + 30] = s;
    }
}

// ---------------- math ----------------
__device__ __forceinline__ float tanh_a(float x) {
    float r; asm("tanh.approx.f32 %0, %1;" : "=f"(r) : "f"(x)); return r;
}
// packed tanh: 2 values per MUFU
__device__ __forceinline__ uint32_t tanh_h2(uint32_t x) {
    uint32_t r; asm("tanh.approx.f16x2 %0, %1;" : "=r"(r) : "r"(x)); return r;
}
__device__ __forceinline__ uint32_t h2u(__half2 h) { return *reinterpret_cast<uint32_t*>(&h); }
__device__ __forceinline__ __half2  u2h(uint32_t u) { return *reinterpret_cast<__half2*>(&u); }
__device__ __forceinline__ float2 h2f(uint32_t u) {
    return __half22float2(u2h(u));
}
// packed sigmoid: sigma(y) = 0.5*tanh(0.5*y) + 0.5  (1 MUFU + 2 HALU per 2 vals)
__device__ __forceinline__ uint32_t sig_h2(uint32_t y) {
    const __half2 h05 = __float2half2_rn(0.5f);
    uint32_t t = tanh_h2(h2u(__hmul2(u2h(y), h05)));
    return h2u(__hfma2(u2h(t), h05, h05));
}

// ---------------- HMMA m16n8k16 f16 ----------------
__device__ __forceinline__ void mma_f16(float d[4], const uint32_t a[4],
                                        uint32_t b0, uint32_t b1) {
    asm volatile("mma.sync.aligned.m16n8k16.row.col.f32.f16.f16.f32 "
        "{%0,%1,%2,%3}, {%4,%5,%6,%7}, {%8,%9}, {%0,%1,%2,%3};"
        : "+f"(d[0]), "+f"(d[1]), "+f"(d[2]), "+f"(d[3])
        : "r"(a[0]), "r"(a[1]), "r"(a[2]), "r"(a[3]), "r"(b0), "r"(b1));
}

// D tile for one nt (16 rows), bias-initialized.
template <int KT>
__device__ __forceinline__ void dense_nt(
    const uint32_t (&aH)[3][4],
    const uint32_t* __restrict__ wfH,
    const float* __restrict__ bias, int nt, int lane, int tq,
    float d[4])
{
    float2 bb = *reinterpret_cast<const float2*>(bias + nt * 8 + tq * 2);
    d[0] = bb.x; d[1] = bb.y; d[2] = bb.x; d[3] = bb.y;
#pragma unroll
    for (int kt = 0; kt < KT; ++kt) {
        uint2 bh = *reinterpret_cast<const uint2*>(wfH + ((nt * KT + kt) * 32 + lane) * 2);
        mma_f16(d, aH[kt], bh.x, bh.y);
    }
}

// value pair -> f16x2, optional packed tanh (applied after f16 rounding)
template <bool TANH>
__device__ __forceinline__ void pack1(float v0, float v1, uint32_t& h) {
    h = pack_f16(v0, v1);
    if (TANH) h = tanh_h2(h);
}

template <bool TANH>
__device__ __forceinline__ void conv_tile(const float de[4], const float dd[4],
                                          uint32_t aH[4]) {
    pack1<TANH>(de[0], de[1], aH[0]);
    pack1<TANH>(de[2], de[3], aH[1]);
    pack1<TANH>(dd[0], dd[1], aH[2]);
    pack1<TANH>(dd[2], dd[3], aH[3]);
}

template <int KT_IN, int NT, int KT_OUT, bool TANH>
__device__ __forceinline__ void run_layer(
    const uint32_t (&inH)[3][4],
    uint32_t (&outH)[3][4],
    const uint32_t* __restrict__ wfH,
    const float* __restrict__ bias, int lane, int tq)
{
#pragma unroll
    for (int ko = 0; ko < KT_OUT; ++ko) {
        float de[4], dd[4];
        dense_nt<KT_IN>(inH, wfH, bias, 2 * ko, lane, tq, de);
        if (2 * ko + 1 < NT) {
            dense_nt<KT_IN>(inH, wfH, bias, 2 * ko + 1, lane, tq, dd);
        } else {
#pragma unroll
            for (int q = 0; q < 4; ++q) dd[q] = 0.0f;
        }
        conv_tile<TANH>(de, dd, outH[ko]);
    }
}

// ---------------- main kernel: 16 rows per warp, 6 CTAs/SM ----------------
__global__ void __launch_bounds__(BLK, 6)
lstm_main(const float* __restrict__ x, float* __restrict__ out, int n)
{
    __shared__ uint32_t swf[SWTOT];
    const int tid = threadIdx.x;
    {
        const uint4* src = reinterpret_cast<const uint4*>(g_wf);
        uint4* dst = reinterpret_cast<uint4*>(swf);
        for (int i = tid; i < SWTOT / 4; i += BLK) dst[i] = src[i];
    }
    __syncthreads();

    const float* sb = reinterpret_cast<const float*>(swf);
    const int lane = tid & 31, warp = tid >> 5;
    const int quad = lane >> 2, tq = lane & 3;

    uint32_t XH[3][4], YH[3][4];
    float c[4][4];
    float p[2];

    const int ntiles = n >> 4;   // 16 rows per tile
    for (int tile = blockIdx.x * 4 + warp; tile < ntiles; tile += GRID * 4) {
        const int rbase = tile << 4;
#pragma unroll
        for (int kt = 0; kt < 3; ++kt)
#pragma unroll
            for (int r = 0; r < 4; ++r) XH[kt][r] = 0u;
#pragma unroll
        for (int a = 0; a < 4; ++a)
#pragma unroll
            for (int q = 0; q < 4; ++q) c[a][q] = 0.0f;
        p[0] = 0.0f; p[1] = 0.0f;

#pragma unroll 1
        for (int t = 0; t < 3; ++t) {
            // x into X kt0 regs0,1 (k = tq*2, rows quad + 8*rh)
#pragma unroll
            for (int rh = 0; rh < 2; ++rh) {
                int row = rbase + rh * 8 + quad;
                float2 xv = *reinterpret_cast<const float2*>(x + (size_t)row * 24 + t * 8 + tq * 2);
                pack1<false>(xv.x, xv.y, XH[0][rh]);
            }

            // composite (HT*L0): [x,h](K38) -> tanh -> 30
            run_layer<3, 4, 2, true>(XH, YH, swf + C_H,  sb + B_C,  lane, tq);
            run_layer<2, 6, 3, true>(YH, XH, swf + L1_H, sb + B_L1, lane, tq);
            run_layer<3, 5, 3, true>(XH, YH, swf + L2_H, sb + B_L2, lane, tq);
            run_layer<3, 4, 2, true>(YH, XH, swf + L3_H, sb + B_L3, lane, tq);

            // GW + gates: input X (KT2); i/f/o/g at nt0, nt0+4, nt0+8, nt0+12.
            // All gate nonlinearities packed f16x2; cell update + tanh(cc) in f32
            // (recurrent accumulator keeps fp32 across timesteps).
            uint32_t nhH[8];
            const bool last = (t == 2);
#pragma unroll
            for (int nt0 = 0; nt0 < 4; ++nt0) {
                float di[4], df[4], dq[4], dg[4];
                dense_nt<2>(XH, swf + GW_H, sb + B_GW, nt0,      lane, tq, di);
                dense_nt<2>(XH, swf + GW_H, sb + B_GW, nt0 + 4,  lane, tq, df);
                dense_nt<2>(XH, swf + GW_H, sb + B_GW, nt0 + 8,  lane, tq, dq);
                dense_nt<2>(XH, swf + GW_H, sb + B_GW, nt0 + 12, lane, tq, dg);
#pragma unroll
                for (int pp = 0; pp < 2; ++pp) {
                    // inner tanh of all four gates, packed (2 vals each)
                    uint32_t yi = tanh_h2(pack_f16(di[2*pp], di[2*pp+1]));
                    uint32_t yf = tanh_h2(pack_f16(df[2*pp], df[2*pp+1]));
                    uint32_t yo = tanh_h2(pack_f16(dq[2*pp], dq[2*pp+1]));
                    uint32_t yg = tanh_h2(pack_f16(dg[2*pp], dg[2*pp+1]));
                    // outer nonlinearity, packed
                    float2 ig = h2f(sig_h2(yi));
                    float2 fg = h2f(sig_h2(yf));
                    float2 og = h2f(sig_h2(yo));
                    float2 gg = h2f(tanh_h2(yg));
                    // cell update in fp32
                    int q = 2 * pp;
                    float cc0 = fmaf(fg.x, c[nt0][q],     ig.x * gg.x);
                    float cc1 = fmaf(fg.y, c[nt0][q + 1], ig.y * gg.y);
                    c[nt0][q]     = cc0;
                    c[nt0][q + 1] = cc1;
                    float hh0 = og.x * tanh_a(cc0);
                    float hh1 = og.y * tanh_a(cc1);
                    if (last) {
                        float2 pw = *reinterpret_cast<const float2*>(sb + HEADW + nt0 * 8 + tq * 2);
                        p[pp] = fmaf(hh0, pw.x, fmaf(hh1, pw.y, p[pp]));
                    }
                    nhH[nt0 * 2 + pp] = pack_f16(hh0, hh1);
                }
            }
            // commit h into X: slot s -> (kt, r) = ((s+2)>>2, (s+2)&3)
#pragma unroll
            for (int s = 0; s < 8; ++s)
                XH[(s + 2) >> 2][(s + 2) & 3] = nhH[s];
        }

        // head: reduce over tq lanes (j-parallel), write rows
        float pb = sb[HEADW + 30];
#pragma unroll
        for (int rh = 0; rh < 2; ++rh) {
            float s = p[rh];
            s += __shfl_xor_sync(0xffffffffu, s, 1);
            s += __shfl_xor_sync(0xffffffffu, s, 2);
            if (tq == 0)
                out[rbase + rh * 8 + quad] = s + pb;
        }
    }
}

// ---------------- launch ----------------
extern "C" void kernel_launch(void* const* d_in, const int* in_sizes, int n_in,
                              void* d_out, int out_size)
{
    const float* x    = (const float*)d_in[0];
    const float* ht_W = (const float*)d_in[1];
    const float* ht_b = (const float*)d_in[2];
    const float* m_W0 = (const float*)d_in[3];
    const float* m_b0 = (const float*)d_in[4];
    const float* m_W1 = (const float*)d_in[5];
    const float* m_b1 = (const float*)d_in[6];
    const float* m_W2 = (const float*)d_in[7];
    const float* m_b2 = (const float*)d_in[8];
    const float* m_W3 = (const float*)d_in[9];
    const float* m_b3 = (const float*)d_in[10];
    const float* gW   = (const float*)d_in[11];
    const float* gb   = (const float*)d_in[12];
    const float* p1W  = (const float*)d_in[13];
    const float* p1b  = (const float*)d_in[14];
    const float* p2W  = (const float*)d_in[15];
    const float* p2b  = (const float*)d_in[16];

    prep_kernel<<<1, 256>>>(ht_W, ht_b, m_W0, m_b0, m_W1, m_b1, m_W2, m_b2,
                            m_W3, m_b3, gW, gb, p1W, p1b, p2W, p2b);

    lstm_main<<<GRID, BLK>>>(x, (float*)d_out, out_size);
}

// round 14
// speedup vs baseline: 1.0885x; 1.0885x over previous
#include <cuda_runtime.h>
#include <cuda_fp16.h>
#include <stdint.h>

#define BLK 128
#define GRID 1184

// ---------------- fragment image offsets (uint32 units) ----------------
// Per layer: [NT][KT][lane(32)][2 regs], single f16 term
constexpr int C_H  = 0;      // composite HT*L0: NT4 KT3 -> 768
constexpr int L1_H = 768;    // NT6 KT2 -> 768
constexpr int L2_H = 1536;   // NT5 KT3 -> 960
constexpr int L3_H = 2496;   // NT4 KT3 -> 768
constexpr int GW_H = 3264;   // NT16 KT2 -> 2048
// biases (float units, same 4B array)
constexpr int B_C = 5312, B_L1 = 5344, B_L2 = 5392, B_L3 = 5432, B_GW = 5464;
constexpr int HEADW = 5592;  // pw[30], pb at 5622
constexpr int SWTOT = 5624;  // 22,496 bytes

__device__ uint32_t g_wf[SWTOT];

__device__ __forceinline__ uint32_t pack_f16(float lo, float hi) {
    uint32_t r; asm("cvt.rn.f16x2.f32 %0, %1, %2;" : "=r"(r) : "f"(hi), "f"(lo)); return r;
}

// ---------------- prep kernel: fold -> f16 B-fragment layout ----------------
__global__ void prep_kernel(
    const float* __restrict__ ht_W, const float* __restrict__ ht_b,
    const float* __restrict__ m_W0, const float* __restrict__ m_b0,
    const float* __restrict__ m_W1, const float* __restrict__ m_b1,
    const float* __restrict__ m_W2, const float* __restrict__ m_b2,
    const float* __restrict__ m_W3, const float* __restrict__ m_b3,
    const float* __restrict__ gW,   const float* __restrict__ gb,
    const float* __restrict__ p1W,  const float* __restrict__ p1b,
    const float* __restrict__ p2W,  const float* __restrict__ p2b)
{
    const int tid = threadIdx.x;
    const int NTH = blockDim.x;

    auto fill = [&](int baseH, int NT, int KT, auto getw) {
        for (int i = tid; i < NT * KT * 64; i += NTH) {
            int reg = i & 1, ln = (i >> 1) & 31, tk = i >> 6;
            int kt = tk % KT, nt = tk / KT;
            int nn = nt * 8 + (ln >> 2);
            int k0 = kt * 16 + (ln & 3) * 2 + reg * 8;
            g_wf[baseH + i] = pack_f16(getw(nn, k0), getw(nn, k0 + 1));
        }
    };

    // composite Wc = W0eff @ ht_W  (30 x 38), exact fp32 fold
    fill(C_H, 4, 3, [&](int n, int k) {
        if (n >= 30 || k >= 38) return 0.0f;
        float s = 0.0f;
        for (int m = 0; m < 30; ++m)
            s += (m_W0[n * 60 + m] + m_W0[n * 60 + 30 + m]) * ht_W[m * 38 + k];
        return s; });
    fill(L1_H, 6, 2, [&](int n, int k) {
        return (n < 45 && k < 30) ? m_W1[n * 30 + k] : 0.0f; });
    fill(L2_H, 5, 3, [&](int n, int k) {
        return (n < 40 && k < 45) ? m_W2[n * 45 + k] : 0.0f; });
    fill(L3_H, 4, 3, [&](int n, int k) {
        return (n < 30 && k < 40) ? m_W3[n * 40 + k] : 0.0f; });
    fill(GW_H, 16, 2, [&](int n, int k) {
        int g = n >> 5, jj = n & 31;
        return (jj < 30 && k < 30) ? gW[(g * 30 + jj) * 30 + k] : 0.0f; });

    float* gf = reinterpret_cast<float*>(g_wf);
    for (int i = tid; i < 32; i += NTH) {
        float s = 0.0f;
        if (i < 30) {
            s = m_b0[i];
            for (int m = 0; m < 30; ++m)
                s += (m_W0[i * 60 + m] + m_W0[i * 60 + 30 + m]) * ht_b[m];
        }
        gf[B_C + i] = s;
    }
    for (int i = tid; i < 48; i += NTH)  gf[B_L1 + i] = (i < 45) ? m_b1[i] : 0.0f;
    for (int i = tid; i < 40; i += NTH)  gf[B_L2 + i] = m_b2[i];
    for (int i = tid; i < 32; i += NTH)  gf[B_L3 + i] = (i < 30) ? m_b3[i] : 0.0f;
    for (int i = tid; i < 128; i += NTH) {
        int g = i >> 5, jj = i & 31;
        gf[B_GW + i] = (jj < 30) ? gb[g * 30 + jj] : 0.0f;
    }
    for (int k = tid; k < 30; k += NTH) {
        float s = 0.0f;
        for (int i = 0; i < 10; ++i) s += p2W[i] * p1W[i * 30 + k];
        gf[HEADW + k] = s;
    }
    if (tid == 0) {
        float s = p2b[0];
        for (int i = 0; i < 10; ++i) s += p2W[i] * p1b[i];
        gf[HEADW + 30] = s;
    }
}

// ---------------- math ----------------
__device__ __forceinline__ float tanh_a(float x) {
    float r; asm("tanh.approx.f32 %0, %1;" : "=f"(r) : "f"(x)); return r;
}
// packed tanh: 2 values per MUFU
__device__ __forceinline__ uint32_t tanh_h2(uint32_t x) {
    uint32_t r; asm("tanh.approx.f16x2 %0, %1;" : "=r"(r) : "r"(x)); return r;
}
__device__ __forceinline__ float2 h2f(uint32_t u) {
    __half2 h = *reinterpret_cast<__half2*>(&u);
    return __half22float2(h);
}
// sigmoid(y) for y in [-1,1]: odd Taylor deg-9, max err ~2e-6, 0 MUFU (R9/R12-verified)
__device__ __forceinline__ float sig_poly(float y) {
    float y2 = y * y;
    float u = fmaf(2.1357273e-5f, y2, -2.1081349e-4f);
    u = fmaf(u, y2, 2.0833333e-3f);
    u = fmaf(u, y2, -2.0833333e-2f);
    u = fmaf(u, y2, 0.25f);
    return fmaf(y, u, 0.5f);
}

// ---------------- HMMA m16n8k16 f16 ----------------
__device__ __forceinline__ void mma_f16(float d[4], const uint32_t a[4],
                                        uint32_t b0, uint32_t b1) {
    asm volatile("mma.sync.aligned.m16n8k16.row.col.f32.f16.f16.f32 "
        "{%0,%1,%2,%3}, {%4,%5,%6,%7}, {%8,%9}, {%0,%1,%2,%3};"
        : "+f"(d[0]), "+f"(d[1]), "+f"(d[2]), "+f"(d[3])
        : "r"(a[0]), "r"(a[1]), "r"(a[2]), "r"(a[3]), "r"(b0), "r"(b1));
}

// D tile for one nt (16 rows), bias-initialized.
template <int KT>
__device__ __forceinline__ void dense_nt(
    const uint32_t (&aH)[3][4],
    const uint32_t* __restrict__ wfH,
    const float* __restrict__ bias, int nt, int lane, int tq,
    float d[4])
{
    float2 bb = *reinterpret_cast<const float2*>(bias + nt * 8 + tq * 2);
    d[0] = bb.x; d[1] = bb.y; d[2] = bb.x; d[3] = bb.y;
#pragma unroll
    for (int kt = 0; kt < KT; ++kt) {
        uint2 bh = *reinterpret_cast<const uint2*>(wfH + ((nt * KT + kt) * 32 + lane) * 2);
        mma_f16(d, aH[kt], bh.x, bh.y);
    }
}

// value pair -> f16x2, optional packed tanh (applied after f16 rounding)
template <bool TANH>
__device__ __forceinline__ void pack1(float v0, float v1, uint32_t& h) {
    h = pack_f16(v0, v1);
    if (TANH) h = tanh_h2(h);
}

template <bool TANH>
__device__ __forceinline__ void conv_tile(const float de[4], const float dd[4],
                                          uint32_t aH[4]) {
    pack1<TANH>(de[0], de[1], aH[0]);
    pack1<TANH>(de[2], de[3], aH[1]);
    pack1<TANH>(dd[0], dd[1], aH[2]);
    pack1<TANH>(dd[2], dd[3], aH[3]);
}

template <int KT_IN, int NT, int KT_OUT, bool TANH>
__device__ __forceinline__ void run_layer(
    const uint32_t (&inH)[3][4],
    uint32_t (&outH)[3][4],
    const uint32_t* __restrict__ wfH,
    const float* __restrict__ bias, int lane, int tq)
{
#pragma unroll
    for (int ko = 0; ko < KT_OUT; ++ko) {
        float de[4], dd[4];
        dense_nt<KT_IN>(inH, wfH, bias, 2 * ko, lane, tq, de);
        if (2 * ko + 1 < NT) {
            dense_nt<KT_IN>(inH, wfH, bias, 2 * ko + 1, lane, tq, dd);
        } else {
#pragma unroll
            for (int q = 0; q < 4; ++q) dd[q] = 0.0f;
        }
        conv_tile<TANH>(de, dd, outH[ko]);
    }
}

// ---------------- main kernel: 16 rows per warp, 8 CTAs/SM ----------------
__global__ void __launch_bounds__(BLK, 8)
lstm_main(const float* __restrict__ x, float* __restrict__ out, int n)
{
    __shared__ uint32_t swf[SWTOT];
    const int tid = threadIdx.x;
    {
        const uint4* src = reinterpret_cast<const uint4*>(g_wf);
        uint4* dst = reinterpret_cast<uint4*>(swf);
        for (int i = tid; i < SWTOT / 4; i += BLK) dst[i] = src[i];
    }
    __syncthreads();

    const float* sb = reinterpret_cast<const float*>(swf);
    const int lane = tid & 31, warp = tid >> 5;
    const int quad = lane >> 2, tq = lane & 3;

    uint32_t XH[3][4], YH[3][4];
    float c[4][4];
    float p[2];

    const int ntiles = n >> 4;   // 16 rows per tile
    for (int tile = blockIdx.x * 4 + warp; tile < ntiles; tile += GRID * 4) {
        const int rbase = tile << 4;
#pragma unroll
        for (int kt = 0; kt < 3; ++kt)
#pragma unroll
            for (int r = 0; r < 4; ++r) XH[kt][r] = 0u;
#pragma unroll
        for (int a = 0; a < 4; ++a)
#pragma unroll
            for (int q = 0; q < 4; ++q) c[a][q] = 0.0f;
        p[0] = 0.0f; p[1] = 0.0f;

#pragma unroll 1
        for (int t = 0; t < 3; ++t) {
            // x into X kt0 regs0,1 (k = tq*2, rows quad + 8*rh)
#pragma unroll
            for (int rh = 0; rh < 2; ++rh) {
                int row = rbase + rh * 8 + quad;
                float2 xv = *reinterpret_cast<const float2*>(x + (size_t)row * 24 + t * 8 + tq * 2);
                pack1<false>(xv.x, xv.y, XH[0][rh]);
            }

            // composite (HT*L0): [x,h](K38) -> tanh -> 30
            run_layer<3, 4, 2, true>(XH, YH, swf + C_H,  sb + B_C,  lane, tq);
            run_layer<2, 6, 3, true>(YH, XH, swf + L1_H, sb + B_L1, lane, tq);
            run_layer<3, 5, 3, true>(XH, YH, swf + L2_H, sb + B_L2, lane, tq);
            run_layer<3, 4, 2, true>(YH, XH, swf + L3_H, sb + B_L3, lane, tq);

            // GW + gates: input X (KT2); i/f/o/g at nt0, nt0+4, nt0+8, nt0+12.
            // inner tanh + g's outer tanh in f16x2 (2 vals/MUFU);
            // i/f/o outer sigma via f32 poly (0 MUFU); cell + tanh(cc) in f32.
            uint32_t nhH[8];
            const bool last = (t == 2);
#pragma unroll
            for (int nt0 = 0; nt0 < 4; ++nt0) {
                float di[4], df[4], dq[4], dg[4];
                dense_nt<2>(XH, swf + GW_H, sb + B_GW, nt0,      lane, tq, di);
                dense_nt<2>(XH, swf + GW_H, sb + B_GW, nt0 + 4,  lane, tq, df);
                dense_nt<2>(XH, swf + GW_H, sb + B_GW, nt0 + 8,  lane, tq, dq);
                dense_nt<2>(XH, swf + GW_H, sb + B_GW, nt0 + 12, lane, tq, dg);
                float hh[4];
#pragma unroll
                for (int pp = 0; pp < 2; ++pp) {
                    uint32_t yi = tanh_h2(pack_f16(di[2*pp], di[2*pp+1]));
                    uint32_t yf = tanh_h2(pack_f16(df[2*pp], df[2*pp+1]));
                    uint32_t yo = tanh_h2(pack_f16(dq[2*pp], dq[2*pp+1]));
                    uint32_t yg = tanh_h2(pack_f16(dg[2*pp], dg[2*pp+1]));
                    uint32_t g2 = tanh_h2(yg);
                    float2 fi = h2f(yi), ff = h2f(yf), fo = h2f(yo), fg2 = h2f(g2);
#pragma unroll
                    for (int e = 0; e < 2; ++e) {
                        int q = 2 * pp + e;
                        float ig = sig_poly(e ? fi.y : fi.x);
                        float fg = sig_poly(e ? ff.y : ff.x);
                        float og = sig_poly(e ? fo.y : fo.x);
                        float gg = e ? fg2.y : fg2.x;
                        float cc = fmaf(fg, c[nt0][q], ig * gg);
                        c[nt0][q] = cc;
                        hh[q] = og * tanh_a(cc);
                    }
                }
                if (last) {
                    float2 pw = *reinterpret_cast<const float2*>(sb + HEADW + nt0 * 8 + tq * 2);
                    p[0] = fmaf(hh[0], pw.x, fmaf(hh[1], pw.y, p[0]));
                    p[1] = fmaf(hh[2], pw.x, fmaf(hh[3], pw.y, p[1]));
                }
                pack1<false>(hh[0], hh[1], nhH[nt0 * 2 + 0]);
                pack1<false>(hh[2], hh[3], nhH[nt0 * 2 + 1]);
            }
            // commit h into X: slot s -> (kt, r) = ((s+2)>>2, (s+2)&3)
#pragma unroll
            for (int s = 0; s < 8; ++s)
                XH[(s + 2) >> 2][(s + 2) & 3] = nhH[s];
        }

        // head: reduce over tq lanes (j-parallel), write rows
        float pb = sb[HEADW + 30];
#pragma unroll
        for (int rh = 0; rh < 2; ++rh) {
            float s = p[rh];
            s += __shfl_xor_sync(0xffffffffu, s, 1);
            s += __shfl_xor_sync(0xffffffffu, s, 2);
            if (tq == 0)
                out[rbase + rh * 8 + quad] = s + pb;
        }
    }
}

// ---------------- launch ----------------
extern "C" void kernel_launch(void* const* d_in, const int* in_sizes, int n_in,
                              void* d_out, int out_size)
{
    const float* x    = (const float*)d_in[0];
    const float* ht_W = (const float*)d_in[1];
    const float* ht_b = (const float*)d_in[2];
    const float* m_W0 = (const float*)d_in[3];
    const float* m_b0 = (const float*)d_in[4];
    const float* m_W1 = (const float*)d_in[5];
    const float* m_b1 = (const float*)d_in[6];
    const float* m_W2 = (const float*)d_in[7];
    const float* m_b2 = (const float*)d_in[8];
    const float* m_W3 = (const float*)d_in[9];
    const float* m_b3 = (const float*)d_in[10];
    const float* gW   = (const float*)d_in[11];
    const float* gb   = (const float*)d_in[12];
    const float* p1W  = (const float*)d_in[13];
    const float* p1b  = (const float*)d_in[14];
    const float* p2W  = (const float*)d_in[15];
    const float* p2b  = (const float*)d_in[16];

    prep_kernel<<<1, 256>>>(ht_W, ht_b, m_W0, m_b0, m_W1, m_b1, m_W2, m_b2,
                            m_W3, m_b3, gW, gb, p1W, p1b, p2W, p2b);

    lstm_main<<<GRID, BLK>>>(x, (float*)d_out, out_size);
}

// round 15
// speedup vs baseline: 1.1776x; 1.0819x over previous
#include <cuda_runtime.h>
#include <cuda_fp16.h>
#include <stdint.h>

#define BLK 128
#define GRID 888

// ---------------- fragment image offsets (uint32 units) ----------------
// Per layer: [NT][KT][lane(32)][2 regs], single f16 term
constexpr int C_H  = 0;      // composite HT*L0: NT4 KT3 -> 768
constexpr int L1_H = 768;    // NT6 KT2 -> 768
constexpr int L2_H = 1536;   // NT5 KT3 -> 960
constexpr int L3_H = 2496;   // NT4 KT3 -> 768
constexpr int GW_H = 3264;   // NT16 KT2 -> 2048
// biases (float units, same 4B array)
constexpr int B_C = 5312, B_L1 = 5344, B_L2 = 5392, B_L3 = 5432, B_GW = 5464;
constexpr int HEADW = 5592;  // pw[30], pb at 5622
constexpr int SWTOT = 5624;  // 22,496 bytes

__device__ uint32_t g_wf[SWTOT];

__device__ __forceinline__ uint32_t pack_f16(float lo, float hi) {
    uint32_t r; asm("cvt.rn.f16x2.f32 %0, %1, %2;" : "=r"(r) : "f"(hi), "f"(lo)); return r;
}

// ---------------- prep kernel: fold -> f16 B-fragment layout ----------------
__global__ void prep_kernel(
    const float* __restrict__ ht_W, const float* __restrict__ ht_b,
    const float* __restrict__ m_W0, const float* __restrict__ m_b0,
    const float* __restrict__ m_W1, const float* __restrict__ m_b1,
    const float* __restrict__ m_W2, const float* __restrict__ m_b2,
    const float* __restrict__ m_W3, const float* __restrict__ m_b3,
    const float* __restrict__ gW,   const float* __restrict__ gb,
    const float* __restrict__ p1W,  const float* __restrict__ p1b,
    const float* __restrict__ p2W,  const float* __restrict__ p2b)
{
    const int tid = threadIdx.x;
    const int NTH = blockDim.x;

    auto fill = [&](int baseH, int NT, int KT, auto getw) {
        for (int i = tid; i < NT * KT * 64; i += NTH) {
            int reg = i & 1, ln = (i >> 1) & 31, tk = i >> 6;
            int kt = tk % KT, nt = tk / KT;
            int nn = nt * 8 + (ln >> 2);
            int k0 = kt * 16 + (ln & 3) * 2 + reg * 8;
            g_wf[baseH + i] = pack_f16(getw(nn, k0), getw(nn, k0 + 1));
        }
    };

    // composite Wc = W0eff @ ht_W  (30 x 38), exact fp32 fold
    fill(C_H, 4, 3, [&](int n, int k) {
        if (n >= 30 || k >= 38) return 0.0f;
        float s = 0.0f;
        for (int m = 0; m < 30; ++m)
            s += (m_W0[n * 60 + m] + m_W0[n * 60 + 30 + m]) * ht_W[m * 38 + k];
        return s; });
    fill(L1_H, 6, 2, [&](int n, int k) {
        return (n < 45 && k < 30) ? m_W1[n * 30 + k] : 0.0f; });
    fill(L2_H, 5, 3, [&](int n, int k) {
        return (n < 40 && k < 45) ? m_W2[n * 45 + k] : 0.0f; });
    fill(L3_H, 4, 3, [&](int n, int k) {
        return (n < 30 && k < 40) ? m_W3[n * 40 + k] : 0.0f; });
    fill(GW_H, 16, 2, [&](int n, int k) {
        int g = n >> 5, jj = n & 31;
        return (jj < 30 && k < 30) ? gW[(g * 30 + jj) * 30 + k] : 0.0f; });

    float* gf = reinterpret_cast<float*>(g_wf);
    for (int i = tid; i < 32; i += NTH) {
        float s = 0.0f;
        if (i < 30) {
            s = m_b0[i];
            for (int m = 0; m < 30; ++m)
                s += (m_W0[i * 60 + m] + m_W0[i * 60 + 30 + m]) * ht_b[m];
        }
        gf[B_C + i] = s;
    }
    for (int i = tid; i < 48; i += NTH)  gf[B_L1 + i] = (i < 45) ? m_b1[i] : 0.0f;
    for (int i = tid; i < 40; i += NTH)  gf[B_L2 + i] = m_b2[i];
    for (int i = tid; i < 32; i += NTH)  gf[B_L3 + i] = (i < 30) ? m_b3[i] : 0.0f;
    for (int i = tid; i < 128; i += NTH) {
        int g = i >> 5, jj = i & 31;
        gf[B_GW + i] = (jj < 30) ? gb[g * 30 + jj] : 0.0f;
    }
    for (int k = tid; k < 30; k += NTH) {
        float s = 0.0f;
        for (int i = 0; i < 10; ++i) s += p2W[i] * p1W[i * 30 + k];
        gf[HEADW + k] = s;
    }
    if (tid == 0) {
        float s = p2b[0];
        for (int i = 0; i < 10; ++i) s += p2W[i] * p1b[i];
        gf[HEADW + 30] = s;
    }
}

// ---------------- math ----------------
__device__ __forceinline__ float tanh_a(float x) {
    float r; asm("tanh.approx.f32 %0, %1;" : "=f"(r) : "f"(x)); return r;
}
// packed tanh: 2 values per MUFU
__device__ __forceinline__ uint32_t tanh_h2(uint32_t x) {
    uint32_t r; asm("tanh.approx.f16x2 %0, %1;" : "=r"(r) : "r"(x)); return r;
}
__device__ __forceinline__ __half2 u2h(uint32_t u) { return *reinterpret_cast<__half2*>(&u); }
__device__ __forceinline__ float2 h2f(uint32_t u) {
    return __half22float2(u2h(u));
}
// packed sigmoid(y) for y in [-1,1]: odd deg-7 Taylor in half2 (0 MUFU, 5 h2 ops / 2 vals)
__device__ __forceinline__ __half2 sig_h2p(__half2 y) {
    const __half2 c7 = __float2half2_rn(-2.1081349e-4f);
    const __half2 c5 = __float2half2_rn( 2.0833333e-3f);
    const __half2 c3 = __float2half2_rn(-2.0833333e-2f);
    const __half2 c1 = __float2half2_rn( 0.25f);
    const __half2 h5 = __float2half2_rn( 0.5f);
    __half2 y2 = __hmul2(y, y);
    __half2 u  = __hfma2(c7, y2, c5);
    u = __hfma2(u, y2, c3);
    u = __hfma2(u, y2, c1);
    return __hfma2(y, u, h5);
}

// ---------------- HMMA m16n8k16 f16 ----------------
__device__ __forceinline__ void mma_f16(float d[4], const uint32_t a[4],
                                        uint32_t b0, uint32_t b1) {
    asm volatile("mma.sync.aligned.m16n8k16.row.col.f32.f16.f16.f32 "
        "{%0,%1,%2,%3}, {%4,%5,%6,%7}, {%8,%9}, {%0,%1,%2,%3};"
        : "+f"(d[0]), "+f"(d[1]), "+f"(d[2]), "+f"(d[3])
        : "r"(a[0]), "r"(a[1]), "r"(a[2]), "r"(a[3]), "r"(b0), "r"(b1));
}

// D tile for one nt (16 rows), bias-initialized.
template <int KT>
__device__ __forceinline__ void dense_nt(
    const uint32_t (&aH)[3][4],
    const uint32_t* __restrict__ wfH,
    const float* __restrict__ bias, int nt, int lane, int tq,
    float d[4])
{
    float2 bb = *reinterpret_cast<const float2*>(bias + nt * 8 + tq * 2);
    d[0] = bb.x; d[1] = bb.y; d[2] = bb.x; d[3] = bb.y;
#pragma unroll
    for (int kt = 0; kt < KT; ++kt) {
        uint2 bh = *reinterpret_cast<const uint2*>(wfH + ((nt * KT + kt) * 32 + lane) * 2);
        mma_f16(d, aH[kt], bh.x, bh.y);
    }
}

// value pair -> f16x2, optional packed tanh (applied after f16 rounding)
template <bool TANH>
__device__ __forceinline__ void pack1(float v0, float v1, uint32_t& h) {
    h = pack_f16(v0, v1);
    if (TANH) h = tanh_h2(h);
}

template <bool TANH>
__device__ __forceinline__ void conv_tile(const float de[4], const float dd[4],
                                          uint32_t aH[4]) {
    pack1<TANH>(de[0], de[1], aH[0]);
    pack1<TANH>(de[2], de[3], aH[1]);
    pack1<TANH>(dd[0], dd[1], aH[2]);
    pack1<TANH>(dd[2], dd[3], aH[3]);
}

template <int KT_IN, int NT, int KT_OUT, bool TANH>
__device__ __forceinline__ void run_layer(
    const uint32_t (&inH)[3][4],
    uint32_t (&outH)[3][4],
    const uint32_t* __restrict__ wfH,
    const float* __restrict__ bias, int lane, int tq)
{
#pragma unroll
    for (int ko = 0; ko < KT_OUT; ++ko) {
        float de[4], dd[4];
        dense_nt<KT_IN>(inH, wfH, bias, 2 * ko, lane, tq, de);
        if (2 * ko + 1 < NT) {
            dense_nt<KT_IN>(inH, wfH, bias, 2 * ko + 1, lane, tq, dd);
        } else {
#pragma unroll
            for (int q = 0; q < 4; ++q) dd[q] = 0.0f;
        }
        conv_tile<TANH>(de, dd, outH[ko]);
    }
}

// ---------------- main kernel: 16 rows per warp, 6 CTAs/SM ----------------
__global__ void __launch_bounds__(BLK, 6)
lstm_main(const float* __restrict__ x, float* __restrict__ out, int n)
{
    __shared__ uint32_t swf[SWTOT];
    const int tid = threadIdx.x;
    {
        const uint4* src = reinterpret_cast<const uint4*>(g_wf);
        uint4* dst = reinterpret_cast<uint4*>(swf);
        for (int i = tid; i < SWTOT / 4; i += BLK) dst[i] = src[i];
    }
    __syncthreads();

    const float* sb = reinterpret_cast<const float*>(swf);
    const int lane = tid & 31, warp = tid >> 5;
    const int quad = lane >> 2, tq = lane & 3;

    uint32_t XH[3][4], YH[3][4];
    float c[4][4];
    float p[2];

    const int ntiles = n >> 4;   // 16 rows per tile
    for (int tile = blockIdx.x * 4 + warp; tile < ntiles; tile += GRID * 4) {
        const int rbase = tile << 4;
#pragma unroll
        for (int kt = 0; kt < 3; ++kt)
#pragma unroll
            for (int r = 0; r < 4; ++r) XH[kt][r] = 0u;
#pragma unroll
        for (int a = 0; a < 4; ++a)
#pragma unroll
            for (int q = 0; q < 4; ++q) c[a][q] = 0.0f;
        p[0] = 0.0f; p[1] = 0.0f;

#pragma unroll 1
        for (int t = 0; t < 3; ++t) {
            // x into X kt0 regs0,1 (k = tq*2, rows quad + 8*rh)
#pragma unroll
            for (int rh = 0; rh < 2; ++rh) {
                int row = rbase + rh * 8 + quad;
                float2 xv = *reinterpret_cast<const float2*>(x + (size_t)row * 24 + t * 8 + tq * 2);
                pack1<false>(xv.x, xv.y, XH[0][rh]);
            }

            // composite (HT*L0): [x,h](K38) -> tanh -> 30
            run_layer<3, 4, 2, true>(XH, YH, swf + C_H,  sb + B_C,  lane, tq);
            run_layer<2, 6, 3, true>(YH, XH, swf + L1_H, sb + B_L1, lane, tq);
            run_layer<3, 5, 3, true>(XH, YH, swf + L2_H, sb + B_L2, lane, tq);
            run_layer<3, 4, 2, true>(YH, XH, swf + L3_H, sb + B_L3, lane, tq);

            // GW + gates: input X (KT2); i/f/o/g at nt0, nt0+4, nt0+8, nt0+12.
            // inner tanh + g's outer tanh f16x2; i/f/o outer sigma via PACKED
            // half2 poly (0 MUFU); cell + tanh(cc) fp32 (recurrence protected).
            uint32_t nhH[8];
            const bool last = (t == 2);
#pragma unroll
            for (int nt0 = 0; nt0 < 4; ++nt0) {
                float di[4], df[4], dq[4], dg[4];
                dense_nt<2>(XH, swf + GW_H, sb + B_GW, nt0,      lane, tq, di);
                dense_nt<2>(XH, swf + GW_H, sb + B_GW, nt0 + 4,  lane, tq, df);
                dense_nt<2>(XH, swf + GW_H, sb + B_GW, nt0 + 8,  lane, tq, dq);
                dense_nt<2>(XH, swf + GW_H, sb + B_GW, nt0 + 12, lane, tq, dg);
                float hh[4];
#pragma unroll
                for (int pp = 0; pp < 2; ++pp) {
                    uint32_t yi = tanh_h2(pack_f16(di[2*pp], di[2*pp+1]));
                    uint32_t yf = tanh_h2(pack_f16(df[2*pp], df[2*pp+1]));
                    uint32_t yo = tanh_h2(pack_f16(dq[2*pp], dq[2*pp+1]));
                    uint32_t yg = tanh_h2(pack_f16(dg[2*pp], dg[2*pp+1]));
                    __half2 gg2 = u2h(tanh_h2(yg));
                    __half2 ig2 = sig_h2p(u2h(yi));
                    __half2 fg2 = sig_h2p(u2h(yf));
                    __half2 og2 = sig_h2p(u2h(yo));
                    __half2 pg  = __hmul2(ig2, gg2);     // i*g packed
                    float2 pf = __half22float2(pg);
                    float2 ff = __half22float2(fg2);
                    float2 of = __half22float2(og2);
                    int q = 2 * pp;
                    float cc0 = fmaf(ff.x, c[nt0][q],     pf.x);
                    float cc1 = fmaf(ff.y, c[nt0][q + 1], pf.y);
                    c[nt0][q]     = cc0;
                    c[nt0][q + 1] = cc1;
                    hh[q]     = of.x * tanh_a(cc0);
                    hh[q + 1] = of.y * tanh_a(cc1);
                }
                if (last) {
                    float2 pw = *reinterpret_cast<const float2*>(sb + HEADW + nt0 * 8 + tq * 2);
                    p[0] = fmaf(hh[0], pw.x, fmaf(hh[1], pw.y, p[0]));
                    p[1] = fmaf(hh[2], pw.x, fmaf(hh[3], pw.y, p[1]));
                }
                pack1<false>(hh[0], hh[1], nhH[nt0 * 2 + 0]);
                pack1<false>(hh[2], hh[3], nhH[nt0 * 2 + 1]);
            }
            // commit h into X: slot s -> (kt, r) = ((s+2)>>2, (s+2)&3)
#pragma unroll
            for (int s = 0; s < 8; ++s)
                XH[(s + 2) >> 2][(s + 2) & 3] = nhH[s];
        }

        // head: reduce over tq lanes (j-parallel), write rows
        float pb = sb[HEADW + 30];
#pragma unroll
        for (int rh = 0; rh < 2; ++rh) {
            float s = p[rh];
            s += __shfl_xor_sync(0xffffffffu, s, 1);
            s += __shfl_xor_sync(0xffffffffu, s, 2);
            if (tq == 0)
                out[rbase + rh * 8 + quad] = s + pb;
        }
    }
}

// ---------------- launch ----------------
extern "C" void kernel_launch(void* const* d_in, const int* in_sizes, int n_in,
                              void* d_out, int out_size)
{
    const float* x    = (const float*)d_in[0];
    const float* ht_W = (const float*)d_in[1];
    const float* ht_b = (const float*)d_in[2];
    const float* m_W0 = (const float*)d_in[3];
    const float* m_b0 = (const float*)d_in[4];
    const float* m_W1 = (const float*)d_in[5];
    const float* m_b1 = (const float*)d_in[6];
    const float* m_W2 = (const float*)d_in[7];
    const float* m_b2 = (const float*)d_in[8];
    const float* m_W3 = (const float*)d_in[9];
    const float* m_b3 = (const float*)d_in[10];
    const float* gW   = (const float*)d_in[11];
    const float* gb   = (const float*)d_in[12];
    const float* p1W  = (const float*)d_in[13];
    const float* p1b  = (const float*)d_in[14];
    const float* p2W  = (const float*)d_in[15];
    const float* p2b  = (const float*)d_in[16];

    prep_kernel<<<1, 256>>>(ht_W, ht_b, m_W0, m_b0, m_W1, m_b1, m_W2, m_b2,
                            m_W3, m_b3, gW, gb, p1W, p1b, p2W, p2b);

    lstm_main<<<GRID, BLK>>>(x, (float*)d_out, out_size);
}

// round 16
// speedup vs baseline: 1.2317x; 1.0459x over previous
#include <cuda_runtime.h>
#include <cuda_fp16.h>
#include <stdint.h>

#define BLK 128
#define GRID 888

// ---------------- fragment image offsets (uint32 units) ----------------
// Weights per layer: [NT][KT][lane(32)][2 regs], f16
constexpr int C_H  = 0;      // composite HT*L0: NT4 KT3 -> 768
constexpr int L1_H = 768;    // NT6 KT2 -> 768
constexpr int L2_H = 1536;   // NT5 KT3 -> 960
constexpr int L3_H = 2496;   // NT4 KT3 -> 768
constexpr int GW_H = 3264;   // NT16 KT2 -> 2048
// packed f16x2 biases: [nt*4 + tq] -> pair (b[nt*8+tq*2], b[nt*8+tq*2+1])
constexpr int PB_C  = 5312;  // 16
constexpr int PB_L1 = 5328;  // 24
constexpr int PB_L2 = 5352;  // 20
constexpr int PB_L3 = 5372;  // 16
constexpr int PB_GW = 5388;  // 64
constexpr int HEADW = 5452;  // 31 floats (pw[30], pb)
constexpr int SWTOT = 5484;  // 21,936 bytes

__device__ uint32_t g_wf[SWTOT];

__device__ __forceinline__ uint32_t pack_f16(float lo, float hi) {
    uint32_t r; asm("cvt.rn.f16x2.f32 %0, %1, %2;" : "=r"(r) : "f"(hi), "f"(lo)); return r;
}

// ---------------- prep kernel ----------------
__global__ void prep_kernel(
    const float* __restrict__ ht_W, const float* __restrict__ ht_b,
    const float* __restrict__ m_W0, const float* __restrict__ m_b0,
    const float* __restrict__ m_W1, const float* __restrict__ m_b1,
    const float* __restrict__ m_W2, const float* __restrict__ m_b2,
    const float* __restrict__ m_W3, const float* __restrict__ m_b3,
    const float* __restrict__ gW,   const float* __restrict__ gb,
    const float* __restrict__ p1W,  const float* __restrict__ p1b,
    const float* __restrict__ p2W,  const float* __restrict__ p2b)
{
    const int tid = threadIdx.x;
    const int NTH = blockDim.x;

    auto fill = [&](int baseH, int NT, int KT, auto getw) {
        for (int i = tid; i < NT * KT * 64; i += NTH) {
            int reg = i & 1, ln = (i >> 1) & 31, tk = i >> 6;
            int kt = tk % KT, nt = tk / KT;
            int nn = nt * 8 + (ln >> 2);
            int k0 = kt * 16 + (ln & 3) * 2 + reg * 8;
            g_wf[baseH + i] = pack_f16(getw(nn, k0), getw(nn, k0 + 1));
        }
    };

    // composite Wc = W0eff @ ht_W  (30 x 38), exact fp32 fold
    fill(C_H, 4, 3, [&](int n, int k) {
        if (n >= 30 || k >= 38) return 0.0f;
        float s = 0.0f;
        for (int m = 0; m < 30; ++m)
            s += (m_W0[n * 60 + m] + m_W0[n * 60 + 30 + m]) * ht_W[m * 38 + k];
        return s; });
    fill(L1_H, 6, 2, [&](int n, int k) {
        return (n < 45 && k < 30) ? m_W1[n * 30 + k] : 0.0f; });
    fill(L2_H, 5, 3, [&](int n, int k) {
        return (n < 40 && k < 45) ? m_W2[n * 45 + k] : 0.0f; });
    fill(L3_H, 4, 3, [&](int n, int k) {
        return (n < 30 && k < 40) ? m_W3[n * 40 + k] : 0.0f; });
    fill(GW_H, 16, 2, [&](int n, int k) {
        int g = n >> 5, jj = n & 31;
        return (jj < 30 && k < 30) ? gW[(g * 30 + jj) * 30 + k] : 0.0f; });

    // packed f16x2 biases
    auto fillb = [&](int base, int NT, auto getb) {
        for (int i = tid; i < NT * 4; i += NTH) {
            int nt = i >> 2, tq = i & 3;
            g_wf[base + i] = pack_f16(getb(nt * 8 + tq * 2), getb(nt * 8 + tq * 2 + 1));
        }
    };
    fillb(PB_C, 4, [&](int j) {
        if (j >= 30) return 0.0f;
        float s = m_b0[j];
        for (int m = 0; m < 30; ++m)
            s += (m_W0[j * 60 + m] + m_W0[j * 60 + 30 + m]) * ht_b[m];
        return s; });
    fillb(PB_L1, 6, [&](int j) { return (j < 45) ? m_b1[j] : 0.0f; });
    fillb(PB_L2, 5, [&](int j) { return (j < 40) ? m_b2[j] : 0.0f; });
    fillb(PB_L3, 4, [&](int j) { return (j < 30) ? m_b3[j] : 0.0f; });
    fillb(PB_GW, 16, [&](int j) {
        int g = j >> 5, jj = j & 31;
        return (jj < 30) ? gb[g * 30 + jj] : 0.0f; });

    float* gf = reinterpret_cast<float*>(g_wf);
    for (int k = tid; k < 30; k += NTH) {
        float s = 0.0f;
        for (int i = 0; i < 10; ++i) s += p2W[i] * p1W[i * 30 + k];
        gf[HEADW + k] = s;
    }
    if (tid == 0) {
        float s = p2b[0];
        for (int i = 0; i < 10; ++i) s += p2W[i] * p1b[i];
        gf[HEADW + 30] = s;
    }
}

// ---------------- math ----------------
__device__ __forceinline__ uint32_t tanh_h2(uint32_t x) {
    uint32_t r; asm("tanh.approx.f16x2 %0, %1;" : "=r"(r) : "r"(x)); return r;
}
__device__ __forceinline__ __half2 u2h(uint32_t u) { return *reinterpret_cast<__half2*>(&u); }
__device__ __forceinline__ uint32_t h2u(__half2 h) { return *reinterpret_cast<uint32_t*>(&h); }
// packed sigmoid(y) for y in [-1,1]: odd deg-7 Taylor in half2 (0 MUFU)
__device__ __forceinline__ __half2 sig_h2p(__half2 y) {
    const __half2 c7 = __float2half2_rn(-2.1081349e-4f);
    const __half2 c5 = __float2half2_rn( 2.0833333e-3f);
    const __half2 c3 = __float2half2_rn(-2.0833333e-2f);
    const __half2 c1 = __float2half2_rn( 0.25f);
    const __half2 h5 = __float2half2_rn( 0.5f);
    __half2 y2 = __hmul2(y, y);
    __half2 u  = __hfma2(c7, y2, c5);
    u = __hfma2(u, y2, c3);
    u = __hfma2(u, y2, c1);
    return __hfma2(y, u, h5);
}

// ---------------- HMMA m16n8k16 f16 D/C (packed accumulators) ----------------
__device__ __forceinline__ void mma_f16h(uint32_t d[2], const uint32_t a[4],
                                         uint32_t b0, uint32_t b1) {
    asm volatile("mma.sync.aligned.m16n8k16.row.col.f16.f16.f16.f16 "
        "{%0,%1}, {%2,%3,%4,%5}, {%6,%7}, {%0,%1};"
        : "+r"(d[0]), "+r"(d[1])
        : "r"(a[0]), "r"(a[1]), "r"(a[2]), "r"(a[3]), "r"(b0), "r"(b1));
}

// D tile for one nt (16 rows), f16 accumulators, bias-initialized.
// d[0] = (row quad, col pair tq*2), d[1] = (row quad+8, same cols).
template <int KT>
__device__ __forceinline__ void dense_h(
    const uint32_t (&aH)[3][4],
    const uint32_t* __restrict__ wfH,
    const uint32_t* __restrict__ pb, int nt, int lane, int tq,
    uint32_t d[2])
{
    uint32_t bb = pb[nt * 4 + tq];
    d[0] = bb; d[1] = bb;
#pragma unroll
    for (int kt = 0; kt < KT; ++kt) {
        uint2 bh = *reinterpret_cast<const uint2*>(wfH + ((nt * KT + kt) * 32 + lane) * 2);
        mma_f16h(d, aH[kt], bh.x, bh.y);
    }
}

// Layer: D regs ARE the next A fragment after packed tanh. Zero cvt.
template <int KT_IN, int NT, int KT_OUT>
__device__ __forceinline__ void run_layer(
    const uint32_t (&inH)[3][4],
    uint32_t (&outH)[3][4],
    const uint32_t* __restrict__ wfH,
    const uint32_t* __restrict__ pb, int lane, int tq)
{
#pragma unroll
    for (int ko = 0; ko < KT_OUT; ++ko) {
        uint32_t de[2], dd[2];
        dense_h<KT_IN>(inH, wfH, pb, 2 * ko, lane, tq, de);
        outH[ko][0] = tanh_h2(de[0]);
        outH[ko][1] = tanh_h2(de[1]);
        if (2 * ko + 1 < NT) {
            dense_h<KT_IN>(inH, wfH, pb, 2 * ko + 1, lane, tq, dd);
            outH[ko][2] = tanh_h2(dd[0]);
            outH[ko][3] = tanh_h2(dd[1]);
        } else {
            outH[ko][2] = 0u;
            outH[ko][3] = 0u;
        }
    }
}

// ---------------- main kernel: 16 rows per warp, 6 CTAs/SM ----------------
__global__ void __launch_bounds__(BLK, 6)
lstm_main(const float* __restrict__ x, float* __restrict__ out, int n)
{
    __shared__ uint32_t swf[SWTOT];
    const int tid = threadIdx.x;
    {
        const uint4* src = reinterpret_cast<const uint4*>(g_wf);
        uint4* dst = reinterpret_cast<uint4*>(swf);
        for (int i = tid; i < SWTOT / 4; i += BLK) dst[i] = src[i];
    }
    __syncthreads();

    const float* sb = reinterpret_cast<const float*>(swf);
    const int lane = tid & 31, warp = tid >> 5;
    const int quad = lane >> 2, tq = lane & 3;

    uint32_t XH[3][4], YH[3][4];
    __half2 ch[4][2];     // cell state, packed pairs [nt0][reg]
    float p[2];

    const int ntiles = n >> 4;   // 16 rows per tile
    for (int tile = blockIdx.x * 4 + warp; tile < ntiles; tile += GRID * 4) {
        const int rbase = tile << 4;
#pragma unroll
        for (int kt = 0; kt < 3; ++kt)
#pragma unroll
            for (int r = 0; r < 4; ++r) XH[kt][r] = 0u;
#pragma unroll
        for (int a = 0; a < 4; ++a)
#pragma unroll
            for (int r = 0; r < 2; ++r) ch[a][r] = __float2half2_rn(0.0f);
        p[0] = 0.0f; p[1] = 0.0f;

#pragma unroll 1
        for (int t = 0; t < 3; ++t) {
            // x into X kt0 regs0,1 (k = tq*2, rows quad + 8*rh)
#pragma unroll
            for (int rh = 0; rh < 2; ++rh) {
                int row = rbase + rh * 8 + quad;
                float2 xv = *reinterpret_cast<const float2*>(x + (size_t)row * 24 + t * 8 + tq * 2);
                XH[0][rh] = pack_f16(xv.x, xv.y);
            }

            // composite (HT*L0): [x,h](K38) -> tanh -> 30
            run_layer<3, 4, 2>(XH, YH, swf + C_H,  swf + PB_C,  lane, tq);
            run_layer<2, 6, 3>(YH, XH, swf + L1_H, swf + PB_L1, lane, tq);
            run_layer<3, 5, 3>(XH, YH, swf + L2_H, swf + PB_L2, lane, tq);
            run_layer<3, 4, 2>(YH, XH, swf + L3_H, swf + PB_L3, lane, tq);

            // GW + gates: input X (KT2); i/f/o/g at nt0, nt0+4, nt0+8, nt0+12.
            // Fully packed f16x2 gate pipeline; cell state half2 (T=3, bounded).
            uint32_t nhH[8];
            const bool last = (t == 2);
#pragma unroll
            for (int nt0 = 0; nt0 < 4; ++nt0) {
                uint32_t di[2], df[2], dq[2], dg[2];
                dense_h<2>(XH, swf + GW_H, swf + PB_GW, nt0,      lane, tq, di);
                dense_h<2>(XH, swf + GW_H, swf + PB_GW, nt0 + 4,  lane, tq, df);
                dense_h<2>(XH, swf + GW_H, swf + PB_GW, nt0 + 8,  lane, tq, dq);
                dense_h<2>(XH, swf + GW_H, swf + PB_GW, nt0 + 12, lane, tq, dg);
#pragma unroll
                for (int r = 0; r < 2; ++r) {
                    uint32_t yi = tanh_h2(di[r]);
                    uint32_t yf = tanh_h2(df[r]);
                    uint32_t yo = tanh_h2(dq[r]);
                    uint32_t gg = tanh_h2(tanh_h2(dg[r]));
                    __half2 ig = sig_h2p(u2h(yi));
                    __half2 fg = sig_h2p(u2h(yf));
                    __half2 og = sig_h2p(u2h(yo));
                    __half2 cc = __hfma2(fg, ch[nt0][r], __hmul2(ig, u2h(gg)));
                    ch[nt0][r] = cc;
                    __half2 hh = __hmul2(og, u2h(tanh_h2(h2u(cc))));
                    nhH[nt0 * 2 + r] = h2u(hh);
                    if (last) {
                        float2 hf = __half22float2(hh);
                        float2 pw = *reinterpret_cast<const float2*>(sb + HEADW + nt0 * 8 + tq * 2);
                        p[r] = fmaf(hf.x, pw.x, fmaf(hf.y, pw.y, p[r]));
                    }
                }
            }
            // commit h into X: slot s -> (kt, r) = ((s+2)>>2, (s+2)&3)
#pragma unroll
            for (int s = 0; s < 8; ++s)
                XH[(s + 2) >> 2][(s + 2) & 3] = nhH[s];
        }

        // head: reduce over tq lanes (j-parallel), write rows
        float pb = sb[HEADW + 30];
#pragma unroll
        for (int rh = 0; rh < 2; ++rh) {
            float s = p[rh];
            s += __shfl_xor_sync(0xffffffffu, s, 1);
            s += __shfl_xor_sync(0xffffffffu, s, 2);
            if (tq == 0)
                out[rbase + rh * 8 + quad] = s + pb;
        }
    }
}

// ---------------- launch ----------------
extern "C" void kernel_launch(void* const* d_in, const int* in_sizes, int n_in,
                              void* d_out, int out_size)
{
    const float* x    = (const float*)d_in[0];
    const float* ht_W = (const float*)d_in[1];
    const float* ht_b = (const float*)d_in[2];
    const float* m_W0 = (const float*)d_in[3];
    const float* m_b0 = (const float*)d_in[4];
    const float* m_W1 = (const float*)d_in[5];
    const float* m_b1 = (const float*)d_in[6];
    const float* m_W2 = (const float*)d_in[7];
    const float* m_b2 = (const float*)d_in[8];
    const float* m_W3 = (const float*)d_in[9];
    const float* m_b3 = (const float*)d_in[10];
    const float* gW   = (const float*)d_in[11];
    const float* gb   = (const float*)d_in[12];
    const float* p1W  = (const float*)d_in[13];
    const float* p1b  = (const float*)d_in[14];
    const float* p2W  = (const float*)d_in[15];
    const float* p2b  = (const float*)d_in[16];

    prep_kernel<<<1, 256>>>(ht_W, ht_b, m_W0, m_b0, m_W1, m_b1, m_W2, m_b2,
                            m_W3, m_b3, gW, gb, p1W, p1b, p2W, p2b);

    lstm_main<<<GRID, BLK>>>(x, (float*)d_out, out_size);
}

// round 17
// speedup vs baseline: 1.2617x; 1.0243x over previous
#include <cuda_runtime.h>
#include <cuda_fp16.h>
#include <stdint.h>

#define BLK 128
#define GRID 1036

// ---------------- fragment image offsets (uint32 units) ----------------
// Weights per layer: [NT][KT][lane(32)][2 regs], f16
constexpr int C_H  = 0;      // composite HT*L0: NT4 KT3 -> 768
constexpr int L1_H = 768;    // NT6 KT2 -> 768
constexpr int L2_H = 1536;   // NT5 KT3 -> 960
constexpr int L3_H = 2496;   // NT4 KT3 -> 768
constexpr int GW_H = 3264;   // NT16 KT2 -> 2048
// packed f16x2 biases: [nt*4 + tq] -> pair (b[nt*8+tq*2], b[nt*8+tq*2+1])
constexpr int PB_C  = 5312;  // 16
constexpr int PB_L1 = 5328;  // 24
constexpr int PB_L2 = 5352;  // 20
constexpr int PB_L3 = 5372;  // 16
constexpr int PB_GW = 5388;  // 64
constexpr int HEADW = 5452;  // 31 floats (pw[30], pb)
constexpr int SWTOT = 5484;  // 21,936 bytes

__device__ uint32_t g_wf[SWTOT];

__device__ __forceinline__ uint32_t pack_f16(float lo, float hi) {
    uint32_t r; asm("cvt.rn.f16x2.f32 %0, %1, %2;" : "=r"(r) : "f"(hi), "f"(lo)); return r;
}

// ---------------- prep kernel ----------------
__global__ void prep_kernel(
    const float* __restrict__ ht_W, const float* __restrict__ ht_b,
    const float* __restrict__ m_W0, const float* __restrict__ m_b0,
    const float* __restrict__ m_W1, const float* __restrict__ m_b1,
    const float* __restrict__ m_W2, const float* __restrict__ m_b2,
    const float* __restrict__ m_W3, const float* __restrict__ m_b3,
    const float* __restrict__ gW,   const float* __restrict__ gb,
    const float* __restrict__ p1W,  const float* __restrict__ p1b,
    const float* __restrict__ p2W,  const float* __restrict__ p2b)
{
    const int tid = threadIdx.x;
    const int NTH = blockDim.x;

    auto fill = [&](int baseH, int NT, int KT, auto getw) {
        for (int i = tid; i < NT * KT * 64; i += NTH) {
            int reg = i & 1, ln = (i >> 1) & 31, tk = i >> 6;
            int kt = tk % KT, nt = tk / KT;
            int nn = nt * 8 + (ln >> 2);
            int k0 = kt * 16 + (ln & 3) * 2 + reg * 8;
            g_wf[baseH + i] = pack_f16(getw(nn, k0), getw(nn, k0 + 1));
        }
    };

    // composite Wc = W0eff @ ht_W  (30 x 38), exact fp32 fold
    fill(C_H, 4, 3, [&](int n, int k) {
        if (n >= 30 || k >= 38) return 0.0f;
        float s = 0.0f;
        for (int m = 0; m < 30; ++m)
            s += (m_W0[n * 60 + m] + m_W0[n * 60 + 30 + m]) * ht_W[m * 38 + k];
        return s; });
    fill(L1_H, 6, 2, [&](int n, int k) {
        return (n < 45 && k < 30) ? m_W1[n * 30 + k] : 0.0f; });
    fill(L2_H, 5, 3, [&](int n, int k) {
        return (n < 40 && k < 45) ? m_W2[n * 45 + k] : 0.0f; });
    fill(L3_H, 4, 3, [&](int n, int k) {
        return (n < 30 && k < 40) ? m_W3[n * 40 + k] : 0.0f; });
    fill(GW_H, 16, 2, [&](int n, int k) {
        int g = n >> 5, jj = n & 31;
        return (jj < 30 && k < 30) ? gW[(g * 30 + jj) * 30 + k] : 0.0f; });

    // packed f16x2 biases
    auto fillb = [&](int base, int NT, auto getb) {
        for (int i = tid; i < NT * 4; i += NTH) {
            int nt = i >> 2, tq = i & 3;
            g_wf[base + i] = pack_f16(getb(nt * 8 + tq * 2), getb(nt * 8 + tq * 2 + 1));
        }
    };
    fillb(PB_C, 4, [&](int j) {
        if (j >= 30) return 0.0f;
        float s = m_b0[j];
        for (int m = 0; m < 30; ++m)
            s += (m_W0[j * 60 + m] + m_W0[j * 60 + 30 + m]) * ht_b[m];
        return s; });
    fillb(PB_L1, 6, [&](int j) { return (j < 45) ? m_b1[j] : 0.0f; });
    fillb(PB_L2, 5, [&](int j) { return (j < 40) ? m_b2[j] : 0.0f; });
    fillb(PB_L3, 4, [&](int j) { return (j < 30) ? m_b3[j] : 0.0f; });
    fillb(PB_GW, 16, [&](int j) {
        int g = j >> 5, jj = j & 31;
        return (jj < 30) ? gb[g * 30 + jj] : 0.0f; });

    float* gf = reinterpret_cast<float*>(g_wf);
    for (int k = tid; k < 30; k += NTH) {
        float s = 0.0f;
        for (int i = 0; i < 10; ++i) s += p2W[i] * p1W[i * 30 + k];
        gf[HEADW + k] = s;
    }
    if (tid == 0) {
        float s = p2b[0];
        for (int i = 0; i < 10; ++i) s += p2W[i] * p1b[i];
        gf[HEADW + 30] = s;
    }
}

// ---------------- math ----------------
__device__ __forceinline__ uint32_t tanh_h2(uint32_t x) {
    uint32_t r; asm("tanh.approx.f16x2 %0, %1;" : "=r"(r) : "r"(x)); return r;
}
__device__ __forceinline__ __half2 u2h(uint32_t u) { return *reinterpret_cast<__half2*>(&u); }
__device__ __forceinline__ uint32_t h2u(__half2 h) { return *reinterpret_cast<uint32_t*>(&h); }
// packed sigmoid(y) for y in [-1,1]: odd deg-7 Taylor in half2 (0 MUFU)
__device__ __forceinline__ __half2 sig_h2p(__half2 y) {
    const __half2 c7 = __float2half2_rn(-2.1081349e-4f);
    const __half2 c5 = __float2half2_rn( 2.0833333e-3f);
    const __half2 c3 = __float2half2_rn(-2.0833333e-2f);
    const __half2 c1 = __float2half2_rn( 0.25f);
    const __half2 h5 = __float2half2_rn( 0.5f);
    __half2 y2 = __hmul2(y, y);
    __half2 u  = __hfma2(c7, y2, c5);
    u = __hfma2(u, y2, c3);
    u = __hfma2(u, y2, c1);
    return __hfma2(y, u, h5);
}

// ---------------- HMMA m16n8k16 f16 D/C (packed accumulators) ----------------
__device__ __forceinline__ void mma_f16h(uint32_t d[2], const uint32_t a[4],
                                         uint32_t b0, uint32_t b1) {
    asm volatile("mma.sync.aligned.m16n8k16.row.col.f16.f16.f16.f16 "
        "{%0,%1}, {%2,%3,%4,%5}, {%6,%7}, {%0,%1};"
        : "+r"(d[0]), "+r"(d[1])
        : "r"(a[0]), "r"(a[1]), "r"(a[2]), "r"(a[3]), "r"(b0), "r"(b1));
}

// D tile for one nt (16 rows), f16 accumulators, bias-initialized.
// d[0] = (row quad, col pair tq*2), d[1] = (row quad+8, same cols).
template <int KT>
__device__ __forceinline__ void dense_h(
    const uint32_t (&aH)[3][4],
    const uint32_t* __restrict__ wfH,
    const uint32_t* __restrict__ pb, int nt, int lane, int tq,
    uint32_t d[2])
{
    uint32_t bb = pb[nt * 4 + tq];
    d[0] = bb; d[1] = bb;
#pragma unroll
    for (int kt = 0; kt < KT; ++kt) {
        uint2 bh = *reinterpret_cast<const uint2*>(wfH + ((nt * KT + kt) * 32 + lane) * 2);
        mma_f16h(d, aH[kt], bh.x, bh.y);
    }
}

// Layer: D regs ARE the next A fragment after packed tanh. Zero cvt.
template <int KT_IN, int NT, int KT_OUT>
__device__ __forceinline__ void run_layer(
    const uint32_t (&inH)[3][4],
    uint32_t (&outH)[3][4],
    const uint32_t* __restrict__ wfH,
    const uint32_t* __restrict__ pb, int lane, int tq)
{
#pragma unroll
    for (int ko = 0; ko < KT_OUT; ++ko) {
        uint32_t de[2], dd[2];
        dense_h<KT_IN>(inH, wfH, pb, 2 * ko, lane, tq, de);
        outH[ko][0] = tanh_h2(de[0]);
        outH[ko][1] = tanh_h2(de[1]);
        if (2 * ko + 1 < NT) {
            dense_h<KT_IN>(inH, wfH, pb, 2 * ko + 1, lane, tq, dd);
            outH[ko][2] = tanh_h2(dd[0]);
            outH[ko][3] = tanh_h2(dd[1]);
        } else {
            outH[ko][2] = 0u;
            outH[ko][3] = 0u;
        }
    }
}

// ---------------- main kernel: 16 rows per warp, 7 CTAs/SM ----------------
__global__ void __launch_bounds__(BLK, 7)
lstm_main(const float* __restrict__ x, float* __restrict__ out, int n)
{
    __shared__ uint32_t swf[SWTOT];
    const int tid = threadIdx.x;
    {
        const uint4* src = reinterpret_cast<const uint4*>(g_wf);
        uint4* dst = reinterpret_cast<uint4*>(swf);
        for (int i = tid; i < SWTOT / 4; i += BLK) dst[i] = src[i];
    }
    __syncthreads();

    const float* sb = reinterpret_cast<const float*>(swf);
    const int lane = tid & 31, warp = tid >> 5;
    const int quad = lane >> 2, tq = lane & 3;

    uint32_t XH[3][4], YH[3][4];
    __half2 ch[4][2];     // cell state, packed pairs [nt0][reg]
    float p[2];

    const int ntiles = n >> 4;   // 16 rows per tile
    for (int tile = blockIdx.x * 4 + warp; tile < ntiles; tile += GRID * 4) {
        const int rbase = tile << 4;
#pragma unroll
        for (int kt = 0; kt < 3; ++kt)
#pragma unroll
            for (int r = 0; r < 4; ++r) XH[kt][r] = 0u;
#pragma unroll
        for (int a = 0; a < 4; ++a)
#pragma unroll
            for (int r = 0; r < 2; ++r) ch[a][r] = __float2half2_rn(0.0f);
        p[0] = 0.0f; p[1] = 0.0f;

#pragma unroll 1
        for (int t = 0; t < 3; ++t) {
            // x into X kt0 regs0,1 (k = tq*2, rows quad + 8*rh)
#pragma unroll
            for (int rh = 0; rh < 2; ++rh) {
                int row = rbase + rh * 8 + quad;
                float2 xv = *reinterpret_cast<const float2*>(x + (size_t)row * 24 + t * 8 + tq * 2);
                XH[0][rh] = pack_f16(xv.x, xv.y);
            }

            // composite (HT*L0): [x,h](K38) -> tanh -> 30
            run_layer<3, 4, 2>(XH, YH, swf + C_H,  swf + PB_C,  lane, tq);
            run_layer<2, 6, 3>(YH, XH, swf + L1_H, swf + PB_L1, lane, tq);
            run_layer<3, 5, 3>(XH, YH, swf + L2_H, swf + PB_L2, lane, tq);
            run_layer<3, 4, 2>(YH, XH, swf + L3_H, swf + PB_L3, lane, tq);

            // GW + gates: input X (KT2); i/f/o/g at nt0, nt0+4, nt0+8, nt0+12.
            // Fully packed f16x2 gate pipeline; cell state half2 (T=3, bounded).
            uint32_t nhH[8];
            const bool last = (t == 2);
#pragma unroll
            for (int nt0 = 0; nt0 < 4; ++nt0) {
                uint32_t di[2], df[2], dq[2], dg[2];
                dense_h<2>(XH, swf + GW_H, swf + PB_GW, nt0,      lane, tq, di);
                dense_h<2>(XH, swf + GW_H, swf + PB_GW, nt0 + 4,  lane, tq, df);
                dense_h<2>(XH, swf + GW_H, swf + PB_GW, nt0 + 8,  lane, tq, dq);
                dense_h<2>(XH, swf + GW_H, swf + PB_GW, nt0 + 12, lane, tq, dg);
#pragma unroll
                for (int r = 0; r < 2; ++r) {
                    uint32_t yi = tanh_h2(di[r]);
                    uint32_t yf = tanh_h2(df[r]);
                    uint32_t yo = tanh_h2(dq[r]);
                    uint32_t gg = tanh_h2(tanh_h2(dg[r]));
                    __half2 ig = sig_h2p(u2h(yi));
                    __half2 fg = sig_h2p(u2h(yf));
                    __half2 og = sig_h2p(u2h(yo));
                    __half2 cc = __hfma2(fg, ch[nt0][r], __hmul2(ig, u2h(gg)));
                    ch[nt0][r] = cc;
                    __half2 hh = __hmul2(og, u2h(tanh_h2(h2u(cc))));
                    nhH[nt0 * 2 + r] = h2u(hh);
                    if (last) {
                        float2 hf = __half22float2(hh);
                        float2 pw = *reinterpret_cast<const float2*>(sb + HEADW + nt0 * 8 + tq * 2);
                        p[r] = fmaf(hf.x, pw.x, fmaf(hf.y, pw.y, p[r]));
                    }
                }
            }
            // commit h into X: slot s -> (kt, r) = ((s+2)>>2, (s+2)&3)
#pragma unroll
            for (int s = 0; s < 8; ++s)
                XH[(s + 2) >> 2][(s + 2) & 3] = nhH[s];
        }

        // head: reduce over tq lanes (j-parallel), write rows
        float pb = sb[HEADW + 30];
#pragma unroll
        for (int rh = 0; rh < 2; ++rh) {
            float s = p[rh];
            s += __shfl_xor_sync(0xffffffffu, s, 1);
            s += __shfl_xor_sync(0xffffffffu, s, 2);
            if (tq == 0)
                out[rbase + rh * 8 + quad] = s + pb;
        }
    }
}

// ---------------- launch ----------------
extern "C" void kernel_launch(void* const* d_in, const int* in_sizes, int n_in,
                              void* d_out, int out_size)
{
    const float* x    = (const float*)d_in[0];
    const float* ht_W = (const float*)d_in[1];
    const float* ht_b = (const float*)d_in[2];
    const float* m_W0 = (const float*)d_in[3];
    const float* m_b0 = (const float*)d_in[4];
    const float* m_W1 = (const float*)d_in[5];
    const float* m_b1 = (const float*)d_in[6];
    const float* m_W2 = (const float*)d_in[7];
    const float* m_b2 = (const float*)d_in[8];
    const float* m_W3 = (const float*)d_in[9];
    const float* m_b3 = (const float*)d_in[10];
    const float* gW   = (const float*)d_in[11];
    const float* gb   = (const float*)d_in[12];
    const float* p1W  = (const float*)d_in[13];
    const float* p1b  = (const float*)d_in[14];
    const float* p2W  = (const float*)d_in[15];
    const float* p2b  = (const float*)d_in[16];

    prep_kernel<<<1, 256>>>(ht_W, ht_b, m_W0, m_b0, m_W1, m_b1, m_W2, m_b2,
                            m_W3, m_b3, gW, gb, p1W, p1b, p2W, p2b);

    lstm_main<<<GRID, BLK>>>(x, (float*)d_out, out_size);
}